// round 14
// baseline (speedup 1.0000x reference)
#include <cuda_runtime.h>
#include <cuda_fp16.h>
#include <math.h>
#include <stdint.h>

#define BB 2
#define SS 2048
#define DDIM 1024
#define HH 16
#define HDIM 64
#define FF 4096
#define MTOK (BB*SS)

// ---------------- scratch ----------------
__device__ __align__(128) float  g_x2 [MTOK*DDIM];
__device__ __align__(128) __half g_h  [MTOK*DDIM];
__device__ __align__(128) __half g_cx [MTOK*DDIM];
__device__ __align__(128) __half g_f  [MTOK*FF];
__device__ __align__(128) __half g_qh [MTOK*DDIM];
__device__ __align__(128) __half g_kh [MTOK*DDIM];
__device__ __align__(128) __half g_v16[MTOK*DDIM];
#define WT_TOTAL 12582912
__device__ __align__(128) __half g_wt [WT_TOTAL];

// ---------------- helpers ----------------
__device__ __forceinline__ uint32_t smem_u32(const void* p) {
    uint32_t a;
    asm("{ .reg .u64 t; cvta.to.shared.u64 t, %1; cvt.u32.u64 %0, t; }" : "=r"(a) : "l"(p));
    return a;
}
__device__ __forceinline__ uint32_t h2u(__half2 v) {
    uint32_t r;
    memcpy(&r, &v, 4);
    return r;
}
__device__ __forceinline__ void cp16(uint32_t dst, const void* src) {
    asm volatile("cp.async.cg.shared.global [%0], [%1], 16;" :: "r"(dst), "l"(src) : "memory");
}
#define CP_COMMIT() asm volatile("cp.async.commit_group;" ::: "memory")
#define CP_WAIT(n)  asm volatile("cp.async.wait_group %0;" :: "n"(n) : "memory")

__device__ __forceinline__ void ldsm4(uint32_t* r, uint32_t addr) {
    asm volatile("ldmatrix.sync.aligned.m8n8.x4.shared.b16 {%0,%1,%2,%3}, [%4];"
        : "=r"(r[0]), "=r"(r[1]), "=r"(r[2]), "=r"(r[3]) : "r"(addr));
}
__device__ __forceinline__ void ldsm4t(uint32_t* r, uint32_t addr) {
    asm volatile("ldmatrix.sync.aligned.m8n8.x4.trans.shared.b16 {%0,%1,%2,%3}, [%4];"
        : "=r"(r[0]), "=r"(r[1]), "=r"(r[2]), "=r"(r[3]) : "r"(addr));
}
__device__ __forceinline__ void mma16816(float* c, const uint32_t* a, const uint32_t* b) {
    asm volatile("mma.sync.aligned.m16n8k16.row.col.f32.f16.f16.f32 "
        "{%0,%1,%2,%3}, {%4,%5,%6,%7}, {%8,%9}, {%0,%1,%2,%3};"
        : "+f"(c[0]), "+f"(c[1]), "+f"(c[2]), "+f"(c[3])
        : "r"(a[0]), "r"(a[1]), "r"(a[2]), "r"(a[3]), "r"(b[0]), "r"(b[1]));
}
__device__ __forceinline__ float gelu_exact(float x) {
    return 0.5f * x * (1.0f + erff(x * 0.70710678118654752f));
}
// fast exp2 (input already in log2 domain), degree-4, rel err ~4e-5; x <= 0 only.
__device__ __forceinline__ float fexp2(float t0) {
    float t = fmaxf(t0, -126.0f);
    float k = t + 12582912.0f;
    int   n = __float_as_int(k) - 0x4B400000;
    float g = (t - (k - 12582912.0f)) * 0.693147180559945f;
    float p = 4.1666667e-2f;
    p = fmaf(p, g, 1.6666667e-1f);
    p = fmaf(p, g, 5.0e-1f);
    p = fmaf(p, g, 1.0f);
    p = fmaf(p, g, 1.0f);
    return p * __int_as_float((n + 127) << 23);
}

// ---------------- LayerNorm -> fp16 ----------------
__global__ __launch_bounds__(256)
void ln_k(const float* __restrict__ x, const float* __restrict__ gg,
          const float* __restrict__ bb, __half* __restrict__ oh)
{
    __shared__ float red[32];
    int row = blockIdx.x, tid = threadIdx.x;
    float4 v = *(const float4*)(x + (size_t)row * DDIM + tid * 4);
    float s = v.x + v.y + v.z + v.w;
    float s2 = v.x*v.x + v.y*v.y + v.z*v.z + v.w*v.w;
    #pragma unroll
    for (int off = 16; off; off >>= 1) {
        s  += __shfl_xor_sync(0xffffffffu, s,  off);
        s2 += __shfl_xor_sync(0xffffffffu, s2, off);
    }
    int warp = tid >> 5, lane = tid & 31;
    if (lane == 0) { red[warp] = s; red[warp + 8] = s2; }
    __syncthreads();
    if (tid == 0) {
        float ts = 0.f, ts2 = 0.f;
        #pragma unroll
        for (int w = 0; w < 8; ++w) { ts += red[w]; ts2 += red[w + 8]; }
        red[16] = ts; red[17] = ts2;
    }
    __syncthreads();
    float mean = red[16] * (1.0f / DDIM);
    float var  = red[17] * (1.0f / DDIM) - mean * mean;
    float inv  = rsqrtf(var + 1e-5f);
    float4 gv = *(const float4*)(gg + tid * 4);
    float4 bv = *(const float4*)(bb + tid * 4);
    float o0 = (v.x-mean)*inv*gv.x + bv.x, o1 = (v.y-mean)*inv*gv.y + bv.y;
    float o2 = (v.z-mean)*inv*gv.z + bv.z, o3 = (v.w-mean)*inv*gv.w + bv.w;
    size_t off = (size_t)row * DDIM + tid * 4;
    ((__half2*)(oh+off))[0] = __floats2half2_rn(o0, o1);
    ((__half2*)(oh+off))[1] = __floats2half2_rn(o2, o3);
}

// ---------------- weight transpose (bid-offset so it can be split) ----------------
__global__ __launch_bounds__(256)
void wtrans_all(const float* __restrict__ Wq, const float* __restrict__ Wk,
                const float* __restrict__ Wv, const float* __restrict__ Wo,
                const float* __restrict__ W1, const float* __restrict__ W2,
                __half* __restrict__ wt, int base)
{
    __shared__ __half sh[64][65];
    int bid = blockIdx.x + base, tid = threadIdx.x;
    const float* W; __half* T; int K, N, t;
    if (bid < 1024) {
        int seg = bid >> 8; t = bid & 255;
        W = seg == 0 ? Wq : seg == 1 ? Wk : seg == 2 ? Wv : Wo;
        T = wt + (size_t)seg * 1048576; K = 1024; N = 1024;
    } else if (bid < 2048) {
        t = bid - 1024; W = W1; T = wt + (size_t)4 * 1048576; K = 1024; N = 4096;
    } else {
        t = bid - 2048; W = W2; T = wt + (size_t)8 * 1048576; K = 4096; N = 1024;
    }
    int nt = N >> 6;
    int n0 = (t % nt) * 64, k0 = (t / nt) * 64;
    for (int idx = tid; idx < 4096; idx += 256) {
        int i = idx >> 6, j = idx & 63;
        sh[i][j] = __float2half_rn(W[(size_t)(k0 + i) * N + n0 + j]);
    }
    __syncthreads();
    for (int idx = tid; idx < 4096; idx += 256) {
        int n = idx >> 6, k = idx & 63;
        T[(size_t)(n0 + n) * K + k0 + k] = sh[k][n];
    }
}

// ---------------- fp16 mma GEMM 128x128, k32 x 4-stage, early prefetch ----------------
#define EPI_QKV  0
#define EPI_GELU 2
#define EPI_RES  3
#define PITCH 80
#define ARR_B (128 * PITCH)
#define STG_B (2 * ARR_B)
#define GSMEM (4 * STG_B)

template<int EPI>
__global__ __launch_bounds__(256, 2)
void mma_gemm(const __half* __restrict__ A, const __half* __restrict__ B,
              float* __restrict__ C, float* __restrict__ C2,
              __half* __restrict__ H1, __half* __restrict__ H3, __half* __restrict__ H5,
              const float* __restrict__ R, int N, int K)
{
    extern __shared__ __align__(1024) char smem[];
    const uint32_t sbase = smem_u32(smem);
    const int tid = threadIdx.x, wid = tid >> 5, l = tid & 31;
    const int m0 = blockIdx.y * 128, n0 = blockIdx.x * 128;
    const int wm = wid >> 1, wn = wid & 1;

    const uint32_t aoff = (uint32_t)((l & 15) * PITCH + (l >> 4) * 16);
    const uint32_t boff = (uint32_t)(((l & 7) + (l >> 4) * 8) * PITCH + ((l >> 3) & 1) * 16);

    float acc[2][8][4];
    #pragma unroll
    for (int i = 0; i < 2; ++i)
        #pragma unroll
        for (int j = 0; j < 8; ++j)
            #pragma unroll
            for (int q = 0; q < 4; ++q) acc[i][j][q] = 0.f;

    const int T = K >> 5;

    auto ld_stage = [&](int s) {
        uint32_t dst = sbase + (uint32_t)((s & 3) * STG_B);
        int ko = s * 32;
        #pragma unroll
        for (int q = 0; q < 2; ++q) {
            int i = tid + q * 256;
            int rr = i >> 2, c = i & 3;
            uint32_t so = dst + (uint32_t)(rr * PITCH + c * 16);
            cp16(so,         A + (size_t)(m0 + rr) * K + ko + c * 8);
            cp16(so + ARR_B, B + (size_t)(n0 + rr) * K + ko + c * 8);
        }
    };

    ld_stage(0); CP_COMMIT();
    ld_stage(1); CP_COMMIT();
    ld_stage(2); CP_COMMIT();

    for (int s = 0; s < T; ++s) {
        CP_WAIT(2);
        __syncthreads();
        // prefetch FIRST: buffer (s+3)&3 == (s-1)&3, whose readers all passed
        // the barrier above; loads overlap this stage's compute.
        if (s + 3 < T) ld_stage(s + 3);
        CP_COMMIT();
        uint32_t buf = sbase + (uint32_t)((s & 3) * STG_B);
        #pragma unroll
        for (int kk = 0; kk < 2; ++kk) {
            uint32_t kb = (uint32_t)(kk * 32);
            uint32_t ah[2][4], bh[8][2];
            #pragma unroll
            for (int i = 0; i < 2; ++i)
                ldsm4(ah[i], buf + (uint32_t)((wm * 32 + i * 16) * PITCH) + aoff + kb);
            #pragma unroll
            for (int jp = 0; jp < 4; ++jp) {
                uint32_t rh[4];
                ldsm4(rh, buf + ARR_B + (uint32_t)((wn * 64 + jp * 16) * PITCH) + boff + kb);
                bh[jp*2+0][0] = rh[0]; bh[jp*2+0][1] = rh[1];
                bh[jp*2+1][0] = rh[2]; bh[jp*2+1][1] = rh[3];
            }
            #pragma unroll
            for (int i = 0; i < 2; ++i)
                #pragma unroll
                for (int j = 0; j < 8; ++j)
                    mma16816(acc[i][j], ah[i], bh[j]);
        }
    }

    #pragma unroll
    for (int i = 0; i < 2; ++i)
        #pragma unroll
        for (int j = 0; j < 8; ++j)
            #pragma unroll
            for (int h2 = 0; h2 < 2; ++h2) {
                int rr = m0 + wm * 32 + i * 16 + (l >> 2) + h2 * 8;
                int col = n0 + wn * 64 + j * 8 + (l & 3) * 2;
                float v0 = acc[i][j][h2 * 2 + 0];
                float v1 = acc[i][j][h2 * 2 + 1];
                if (EPI == EPI_QKV) {
                    int seg = col >> 10, cc = col & 1023;
                    int bb2 = rr >> 11, sx = rr & 2047;
                    int hidx = cc >> 6, hd = cc & 63;
                    size_t off = (((size_t)(bb2 * HH + hidx)) * SS + sx) * HDIM + hd;
                    if (seg == 0) {
                        // q scaled by 1/sqrt(64) * log2(e) for log2-domain softmax
                        *(__half2*)(H1 + off) =
                            __floats2half2_rn(v0 * 0.180336879f, v1 * 0.180336879f);
                    } else if (seg == 1) {
                        float2 o; o.x = v0; o.y = v1;
                        *(float2*)(C + off) = o;
                        *(__half2*)(H3 + off) = __floats2half2_rn(v0, v1);
                    } else {
                        float2 o; o.x = v0; o.y = v1;
                        *(float2*)(C2 + off) = o;
                        *(__half2*)(H5 + off) = __floats2half2_rn(v0, v1);
                    }
                } else if (EPI == EPI_GELU) {
                    v0 = gelu_exact(v0); v1 = gelu_exact(v1);
                    *(__half2*)(H1 + (size_t)rr * N + col) = __floats2half2_rn(v0, v1);
                } else {
                    size_t off = (size_t)rr * N + col;
                    float2 rv = *(const float2*)(R + off);
                    float2 o; o.x = v0 + rv.x; o.y = v1 + rv.y;
                    *(float2*)(C + off) = o;
                }
            }
}

// ---------------- tensor-core flash attention: fp16 QK, log2-domain softmax ----------------
#define QP 144
#define FQ_B (128 * QP)
#define FKV_B (64 * QP)
#define FSTG_B (2 * FKV_B)
#define FSMEM (FQ_B + 2 * FSTG_B)

__global__ __launch_bounds__(256, 2)
void flash_tc(const __half* __restrict__ qh, const __half* __restrict__ kh,
              const __half* __restrict__ vv, __half* __restrict__ cx)
{
    extern __shared__ __align__(1024) char smem[];
    const uint32_t sb = smem_u32(smem);
    const int bh = blockIdx.y;
    const int b = bh >> 4, h = bh & 15;
    const int tid = threadIdx.x, wid = tid >> 5, l = tid & 31;

    const uint32_t aoff = (uint32_t)((l & 15) * QP + (l >> 4) * 16);
    const uint32_t boff = (uint32_t)(((l & 7) + (l >> 4) * 8) * QP + ((l >> 3) & 1) * 16);
    const uint32_t voff = (uint32_t)(((l & 7) + ((l >> 3) & 1) * 8) * QP + (l >> 4) * 16);

    #pragma unroll 1
    for (int tt = 0; tt < 2; ++tt) {
        const int qt = tt == 0 ? (int)blockIdx.x : 15 - (int)blockIdx.x;
        const int q0 = qt * 128;

        const __half* qhb = qh + ((size_t)bh * SS + q0) * HDIM;
        #pragma unroll
        for (int i = 0; i < 4; ++i) {
            int idx = tid + i * 256;
            int r = idx >> 3, c = idx & 7;
            cp16(sb + (uint32_t)(r * QP + c * 16), qhb + r * 64 + c * 8);
        }
        CP_COMMIT();

        const int nkt = qt * 2 + 2;
        auto ld_kv = [&](int kt2) {
            uint32_t dstb = sb + FQ_B + (uint32_t)((kt2 & 1) * FSTG_B);
            const __half* kbp = kh + ((size_t)bh * SS + kt2 * 64) * HDIM;
            const __half* vbp = vv + ((size_t)bh * SS + kt2 * 64) * HDIM;
            #pragma unroll
            for (int i = 0; i < 2; ++i) {
                int idx = tid + i * 256;
                int r = idx >> 3, c = idx & 7;
                uint32_t so = (uint32_t)(r * QP + c * 16);
                cp16(dstb + so,         kbp + r * 64 + c * 8);
                cp16(dstb + FKV_B + so, vbp + r * 64 + c * 8);
            }
        };
        ld_kv(0); CP_COMMIT();

        float m2[2] = {-1e30f, -1e30f}, l2[2] = {0.f, 0.f};
        float O[8][4];
        #pragma unroll
        for (int j = 0; j < 8; ++j)
            #pragma unroll
            for (int q = 0; q < 4; ++q) O[j][q] = 0.f;

        for (int kt = 0; kt < nkt; ++kt) {
            CP_WAIT(0);
            __syncthreads();
            if (kt + 1 < nkt) { ld_kv(kt + 1); CP_COMMIT(); }

            uint32_t kb = sb + FQ_B + (uint32_t)((kt & 1) * FSTG_B);
            float S[8][4];
            #pragma unroll
            for (int j = 0; j < 8; ++j)
                #pragma unroll
                for (int q = 0; q < 4; ++q) S[j][q] = 0.f;

            #pragma unroll
            for (int ks = 0; ks < 4; ++ks) {
                uint32_t kadd = (uint32_t)(ks * 32);
                uint32_t aH[4];
                ldsm4(aH, sb + (uint32_t)(wid * 16 * QP) + aoff + kadd);
                #pragma unroll
                for (int jp = 0; jp < 4; ++jp) {
                    uint32_t rH[4];
                    ldsm4(rH, kb + (uint32_t)(jp * 16 * QP) + boff + kadd);
                    uint32_t bH0[2] = {rH[0], rH[1]}, bH1[2] = {rH[2], rH[3]};
                    mma16816(S[jp*2+0], aH, bH0);
                    mma16816(S[jp*2+1], aH, bH1);
                }
            }

            if (kt * 64 + 63 > q0 + wid * 16) {
                int rowb = q0 + wid * 16 + (l >> 2);
                int colb = kt * 64 + 2 * (l & 3);
                #pragma unroll
                for (int j = 0; j < 8; ++j)
                    #pragma unroll
                    for (int q = 0; q < 4; ++q) {
                        int row = rowb + (q >> 1) * 8;
                        int col = colb + 8 * j + (q & 1);
                        if (col > row) S[j][q] = -3.0e38f;
                    }
            }

            #pragma unroll
            for (int h2 = 0; h2 < 2; ++h2) {
                float rm = -3.4e38f;
                #pragma unroll
                for (int j = 0; j < 8; ++j)
                    rm = fmaxf(rm, fmaxf(S[j][h2*2], S[j][h2*2+1]));
                rm = fmaxf(rm, __shfl_xor_sync(0xffffffffu, rm, 1));
                rm = fmaxf(rm, __shfl_xor_sync(0xffffffffu, rm, 2));
                float mn = fmaxf(m2[h2], rm);
                float sc = fexp2(m2[h2] - mn);
                float rs = 0.f;
                #pragma unroll
                for (int j = 0; j < 8; ++j) {
                    float p0 = fexp2(S[j][h2*2]   - mn);
                    float p1 = fexp2(S[j][h2*2+1] - mn);
                    S[j][h2*2] = p0; S[j][h2*2+1] = p1;
                    rs += p0 + p1;
                }
                rs += __shfl_xor_sync(0xffffffffu, rs, 1);
                rs += __shfl_xor_sync(0xffffffffu, rs, 2);
                l2[h2] = l2[h2] * sc + rs;
                m2[h2] = mn;
                #pragma unroll
                for (int j = 0; j < 8; ++j) {
                    O[j][h2*2] *= sc; O[j][h2*2+1] *= sc;
                }
            }

            #pragma unroll
            for (int t = 0; t < 4; ++t) {
                uint32_t aP[4];
                aP[0] = h2u(__floats2half2_rn(S[2*t][0],   S[2*t][1]));
                aP[1] = h2u(__floats2half2_rn(S[2*t][2],   S[2*t][3]));
                aP[2] = h2u(__floats2half2_rn(S[2*t+1][0], S[2*t+1][1]));
                aP[3] = h2u(__floats2half2_rn(S[2*t+1][2], S[2*t+1][3]));
                #pragma unroll
                for (int jp = 0; jp < 4; ++jp) {
                    uint32_t rV[4];
                    ldsm4t(rV, kb + FKV_B + (uint32_t)(t * 16 * QP) + voff + (uint32_t)(jp * 32));
                    uint32_t b0[2] = {rV[0], rV[1]}, b1[2] = {rV[2], rV[3]};
                    mma16816(O[jp*2+0], aP, b0);
                    mma16816(O[jp*2+1], aP, b1);
                }
            }
        }

        #pragma unroll
        for (int h2 = 0; h2 < 2; ++h2) {
            float inv = 1.0f / l2[h2];
            int row = q0 + wid * 16 + (l >> 2) + h2 * 8;
            size_t base = ((size_t)b * SS + row) * DDIM + h * HDIM + 2 * (l & 3);
            #pragma unroll
            for (int j = 0; j < 8; ++j)
                *(__half2*)(cx + base + 8 * j) =
                    __floats2half2_rn(O[j][h2*2] * inv, O[j][h2*2+1] * inv);
        }
        __syncthreads();   // guard Q buffer overwrite by next tt iteration
    }
}

// ---------------- launch ----------------
extern "C" void kernel_launch(void* const* d_in, const int* in_sizes, int n_in,
                              void* d_out, int out_size)
{
    const float* x    = (const float*)d_in[0];
    const float* ln1g = (const float*)d_in[2];
    const float* ln1b = (const float*)d_in[3];
    const float* Wq   = (const float*)d_in[4];
    const float* Wk   = (const float*)d_in[5];
    const float* Wv   = (const float*)d_in[6];
    const float* Wo   = (const float*)d_in[7];
    const float* ln2g = (const float*)d_in[8];
    const float* ln2b = (const float*)d_in[9];
    const float* W1   = (const float*)d_in[10];
    const float* W2   = (const float*)d_in[11];

    float* out  = (float*)d_out;
    float* kout = out  + (size_t)MTOK * DDIM;
    float* vout = kout + (size_t)MTOK * DDIM;

    float *x2; __half *hh, *cx, *fx, *wt, *qh, *kh, *v16;
    cudaGetSymbolAddress((void**)&x2,  g_x2);
    cudaGetSymbolAddress((void**)&hh,  g_h);
    cudaGetSymbolAddress((void**)&cx,  g_cx);
    cudaGetSymbolAddress((void**)&fx,  g_f);
    cudaGetSymbolAddress((void**)&wt,  g_wt);
    cudaGetSymbolAddress((void**)&qh,  g_qh);
    cudaGetSymbolAddress((void**)&kh,  g_kh);
    cudaGetSymbolAddress((void**)&v16, g_v16);

    const size_t M1 = 1048576;
    __half *wqkv = wt, *wo = wt + 3*M1, *w1 = wt + 4*M1, *w2 = wt + 8*M1;

    static cudaStream_t s2 = nullptr;
    static cudaEvent_t evRoot = nullptr, evA = nullptr, evB = nullptr;
    if (!s2) {
        cudaStreamCreateWithFlags(&s2, cudaStreamNonBlocking);
        cudaEventCreateWithFlags(&evRoot, cudaEventDisableTiming);
        cudaEventCreateWithFlags(&evA,    cudaEventDisableTiming);
        cudaEventCreateWithFlags(&evB,    cudaEventDisableTiming);
    }

    cudaFuncSetAttribute(flash_tc, cudaFuncAttributeMaxDynamicSharedMemorySize, FSMEM);
    cudaFuncSetAttribute(mma_gemm<EPI_QKV>,  cudaFuncAttributeMaxDynamicSharedMemorySize, GSMEM);
    cudaFuncSetAttribute(mma_gemm<EPI_GELU>, cudaFuncAttributeMaxDynamicSharedMemorySize, GSMEM);
    cudaFuncSetAttribute(mma_gemm<EPI_RES>,  cudaFuncAttributeMaxDynamicSharedMemorySize, GSMEM);

    dim3 gQKV(3 * DDIM / 128, MTOK / 128);   // (24, 32)
    dim3 gD  (DDIM / 128, MTOK / 128);       // (8, 32)
    dim3 gF  (FF   / 128, MTOK / 128);       // (32, 32)

    // fork: weight transposes on side stream
    cudaEventRecord(evRoot, 0);
    cudaStreamWaitEvent(s2, evRoot, 0);
    wtrans_all<<<1024, 256, 0, s2>>>(Wq, Wk, Wv, Wo, W1, W2, wt, 0);     // Wq,Wk,Wv,Wo
    cudaEventRecord(evA, s2);
    wtrans_all<<<2048, 256, 0, s2>>>(Wq, Wk, Wv, Wo, W1, W2, wt, 1024);  // W1,W2
    cudaEventRecord(evB, s2);

    // main stream
    ln_k<<<MTOK, 256>>>(x, ln1g, ln1b, hh);
    cudaStreamWaitEvent(0, evA, 0);
    mma_gemm<EPI_QKV><<<gQKV, 256, GSMEM>>>(hh, wqkv, kout, vout, qh, kh, v16, nullptr, 3*DDIM, DDIM);
    flash_tc<<<dim3(SS / 256, BB * HH), 256, FSMEM>>>(qh, kh, v16, cx);
    mma_gemm<EPI_RES><<<gD, 256, GSMEM>>>(cx, wo, x2, nullptr, nullptr, nullptr, nullptr, x, DDIM, DDIM);
    ln_k<<<MTOK, 256>>>(x2, ln2g, ln2b, hh);
    cudaStreamWaitEvent(0, evB, 0);
    mma_gemm<EPI_GELU><<<gF, 256, GSMEM>>>(hh, w1, nullptr, nullptr, fx, nullptr, nullptr, nullptr, FF, DDIM);
    mma_gemm<EPI_RES><<<gD, 256, GSMEM>>>(fx, w2, out, nullptr, nullptr, nullptr, nullptr, x2, DDIM, FF);
}

// round 15
// speedup vs baseline: 1.0461x; 1.0461x over previous
#include <cuda_runtime.h>
#include <cuda_fp16.h>
#include <math.h>
#include <stdint.h>

#define BB 2
#define SS 2048
#define DDIM 1024
#define HH 16
#define HDIM 64
#define FF 4096
#define MTOK (BB*SS)

// ---------------- scratch ----------------
__device__ __align__(128) float  g_x2 [MTOK*DDIM];
__device__ __align__(128) __half g_h  [MTOK*DDIM];
__device__ __align__(128) __half g_cx [MTOK*DDIM];
__device__ __align__(128) __half g_f  [MTOK*FF];
__device__ __align__(128) __half g_qh [MTOK*DDIM];
__device__ __align__(128) __half g_kh [MTOK*DDIM];
__device__ __align__(128) __half g_v16[MTOK*DDIM];
#define WT_TOTAL 12582912
__device__ __align__(128) __half g_wt [WT_TOTAL];

// ---------------- helpers ----------------
__device__ __forceinline__ uint32_t smem_u32(const void* p) {
    uint32_t a;
    asm("{ .reg .u64 t; cvta.to.shared.u64 t, %1; cvt.u32.u64 %0, t; }" : "=r"(a) : "l"(p));
    return a;
}
__device__ __forceinline__ uint32_t h2u(__half2 v) {
    uint32_t r;
    memcpy(&r, &v, 4);
    return r;
}
__device__ __forceinline__ void cp16(uint32_t dst, const void* src) {
    asm volatile("cp.async.cg.shared.global [%0], [%1], 16;" :: "r"(dst), "l"(src) : "memory");
}
#define CP_COMMIT() asm volatile("cp.async.commit_group;" ::: "memory")
#define CP_WAIT(n)  asm volatile("cp.async.wait_group %0;" :: "n"(n) : "memory")

__device__ __forceinline__ void ldsm4(uint32_t* r, uint32_t addr) {
    asm volatile("ldmatrix.sync.aligned.m8n8.x4.shared.b16 {%0,%1,%2,%3}, [%4];"
        : "=r"(r[0]), "=r"(r[1]), "=r"(r[2]), "=r"(r[3]) : "r"(addr));
}
__device__ __forceinline__ void ldsm4t(uint32_t* r, uint32_t addr) {
    asm volatile("ldmatrix.sync.aligned.m8n8.x4.trans.shared.b16 {%0,%1,%2,%3}, [%4];"
        : "=r"(r[0]), "=r"(r[1]), "=r"(r[2]), "=r"(r[3]) : "r"(addr));
}
__device__ __forceinline__ void mma16816(float* c, const uint32_t* a, const uint32_t* b) {
    asm volatile("mma.sync.aligned.m16n8k16.row.col.f32.f16.f16.f32 "
        "{%0,%1,%2,%3}, {%4,%5,%6,%7}, {%8,%9}, {%0,%1,%2,%3};"
        : "+f"(c[0]), "+f"(c[1]), "+f"(c[2]), "+f"(c[3])
        : "r"(a[0]), "r"(a[1]), "r"(a[2]), "r"(a[3]), "r"(b[0]), "r"(b[1]));
}
__device__ __forceinline__ float gelu_exact(float x) {
    return 0.5f * x * (1.0f + erff(x * 0.70710678118654752f));
}
// fast exp2 (log2-domain input), degree-4, rel err ~4e-5; x <= 0 only.
__device__ __forceinline__ float fexp2(float t0) {
    float t = fmaxf(t0, -126.0f);
    float k = t + 12582912.0f;
    int   n = __float_as_int(k) - 0x4B400000;
    float g = (t - (k - 12582912.0f)) * 0.693147180559945f;
    float p = 4.1666667e-2f;
    p = fmaf(p, g, 1.6666667e-1f);
    p = fmaf(p, g, 5.0e-1f);
    p = fmaf(p, g, 1.0f);
    p = fmaf(p, g, 1.0f);
    return p * __int_as_float((n + 127) << 23);
}

// ---------------- LayerNorm -> fp16 ----------------
__global__ __launch_bounds__(256)
void ln_k(const float* __restrict__ x, const float* __restrict__ gg,
          const float* __restrict__ bb, __half* __restrict__ oh)
{
    __shared__ float red[32];
    int row = blockIdx.x, tid = threadIdx.x;
    float4 v = *(const float4*)(x + (size_t)row * DDIM + tid * 4);
    float s = v.x + v.y + v.z + v.w;
    float s2 = v.x*v.x + v.y*v.y + v.z*v.z + v.w*v.w;
    #pragma unroll
    for (int off = 16; off; off >>= 1) {
        s  += __shfl_xor_sync(0xffffffffu, s,  off);
        s2 += __shfl_xor_sync(0xffffffffu, s2, off);
    }
    int warp = tid >> 5, lane = tid & 31;
    if (lane == 0) { red[warp] = s; red[warp + 8] = s2; }
    __syncthreads();
    if (tid == 0) {
        float ts = 0.f, ts2 = 0.f;
        #pragma unroll
        for (int w = 0; w < 8; ++w) { ts += red[w]; ts2 += red[w + 8]; }
        red[16] = ts; red[17] = ts2;
    }
    __syncthreads();
    float mean = red[16] * (1.0f / DDIM);
    float var  = red[17] * (1.0f / DDIM) - mean * mean;
    float inv  = rsqrtf(var + 1e-5f);
    float4 gv = *(const float4*)(gg + tid * 4);
    float4 bv = *(const float4*)(bb + tid * 4);
    float o0 = (v.x-mean)*inv*gv.x + bv.x, o1 = (v.y-mean)*inv*gv.y + bv.y;
    float o2 = (v.z-mean)*inv*gv.z + bv.z, o3 = (v.w-mean)*inv*gv.w + bv.w;
    size_t off = (size_t)row * DDIM + tid * 4;
    ((__half2*)(oh+off))[0] = __floats2half2_rn(o0, o1);
    ((__half2*)(oh+off))[1] = __floats2half2_rn(o2, o3);
}

// ---------------- merged weight transpose ----------------
__global__ __launch_bounds__(256)
void wtrans_all(const float* __restrict__ Wq, const float* __restrict__ Wk,
                const float* __restrict__ Wv, const float* __restrict__ Wo,
                const float* __restrict__ W1, const float* __restrict__ W2,
                __half* __restrict__ wt)
{
    __shared__ __half sh[64][65];
    int bid = blockIdx.x, tid = threadIdx.x;
    const float* W; __half* T; int K, N, t;
    if (bid < 1024) {
        int seg = bid >> 8; t = bid & 255;
        W = seg == 0 ? Wq : seg == 1 ? Wk : seg == 2 ? Wv : Wo;
        T = wt + (size_t)seg * 1048576; K = 1024; N = 1024;
    } else if (bid < 2048) {
        t = bid - 1024; W = W1; T = wt + (size_t)4 * 1048576; K = 1024; N = 4096;
    } else {
        t = bid - 2048; W = W2; T = wt + (size_t)8 * 1048576; K = 4096; N = 1024;
    }
    int nt = N >> 6;
    int n0 = (t % nt) * 64, k0 = (t / nt) * 64;
    for (int idx = tid; idx < 4096; idx += 256) {
        int i = idx >> 6, j = idx & 63;
        sh[i][j] = __float2half_rn(W[(size_t)(k0 + i) * N + n0 + j]);
    }
    __syncthreads();
    for (int idx = tid; idx < 4096; idx += 256) {
        int n = idx >> 6, k = idx & 63;
        T[(size_t)(n0 + n) * K + k0 + k] = sh[k][n];
    }
}

// ---------------- fp16 mma GEMM 128x128, k32 x 4-stage (R13 proven) ----------------
#define EPI_QKV  0
#define EPI_GELU 2
#define EPI_RES  3
#define PITCH 80
#define ARR_B (128 * PITCH)
#define STG_B (2 * ARR_B)
#define GSMEM (4 * STG_B)

template<int EPI>
__global__ __launch_bounds__(256, 2)
void mma_gemm(const __half* __restrict__ A, const __half* __restrict__ B,
              float* __restrict__ C, float* __restrict__ C2,
              __half* __restrict__ H1, __half* __restrict__ H3, __half* __restrict__ H5,
              const float* __restrict__ R, int N, int K)
{
    extern __shared__ __align__(1024) char smem[];
    const uint32_t sbase = smem_u32(smem);
    const int tid = threadIdx.x, wid = tid >> 5, l = tid & 31;
    const int m0 = blockIdx.y * 128, n0 = blockIdx.x * 128;
    const int wm = wid >> 1, wn = wid & 1;

    const uint32_t aoff = (uint32_t)((l & 15) * PITCH + (l >> 4) * 16);
    const uint32_t boff = (uint32_t)(((l & 7) + (l >> 4) * 8) * PITCH + ((l >> 3) & 1) * 16);

    float acc[2][8][4];
    #pragma unroll
    for (int i = 0; i < 2; ++i)
        #pragma unroll
        for (int j = 0; j < 8; ++j)
            #pragma unroll
            for (int q = 0; q < 4; ++q) acc[i][j][q] = 0.f;

    const int T = K >> 5;

    auto ld_stage = [&](int s) {
        uint32_t dst = sbase + (uint32_t)((s & 3) * STG_B);
        int ko = s * 32;
        #pragma unroll
        for (int q = 0; q < 2; ++q) {
            int i = tid + q * 256;
            int rr = i >> 2, c = i & 3;
            uint32_t so = dst + (uint32_t)(rr * PITCH + c * 16);
            cp16(so,         A + (size_t)(m0 + rr) * K + ko + c * 8);
            cp16(so + ARR_B, B + (size_t)(n0 + rr) * K + ko + c * 8);
        }
    };

    ld_stage(0); CP_COMMIT();
    ld_stage(1); CP_COMMIT();
    ld_stage(2); CP_COMMIT();

    for (int s = 0; s < T; ++s) {
        CP_WAIT(2);
        __syncthreads();
        uint32_t buf = sbase + (uint32_t)((s & 3) * STG_B);
        #pragma unroll
        for (int kk = 0; kk < 2; ++kk) {
            uint32_t kb = (uint32_t)(kk * 32);
            uint32_t ah[2][4], bh[8][2];
            #pragma unroll
            for (int i = 0; i < 2; ++i)
                ldsm4(ah[i], buf + (uint32_t)((wm * 32 + i * 16) * PITCH) + aoff + kb);
            #pragma unroll
            for (int jp = 0; jp < 4; ++jp) {
                uint32_t rh[4];
                ldsm4(rh, buf + ARR_B + (uint32_t)((wn * 64 + jp * 16) * PITCH) + boff + kb);
                bh[jp*2+0][0] = rh[0]; bh[jp*2+0][1] = rh[1];
                bh[jp*2+1][0] = rh[2]; bh[jp*2+1][1] = rh[3];
            }
            #pragma unroll
            for (int i = 0; i < 2; ++i)
                #pragma unroll
                for (int j = 0; j < 8; ++j)
                    mma16816(acc[i][j], ah[i], bh[j]);
        }
        if (s + 3 < T) ld_stage(s + 3);
        CP_COMMIT();
    }

    #pragma unroll
    for (int i = 0; i < 2; ++i)
        #pragma unroll
        for (int j = 0; j < 8; ++j)
            #pragma unroll
            for (int h2 = 0; h2 < 2; ++h2) {
                int rr = m0 + wm * 32 + i * 16 + (l >> 2) + h2 * 8;
                int col = n0 + wn * 64 + j * 8 + (l & 3) * 2;
                float v0 = acc[i][j][h2 * 2 + 0];
                float v1 = acc[i][j][h2 * 2 + 1];
                if (EPI == EPI_QKV) {
                    int seg = col >> 10, cc = col & 1023;
                    int bb2 = rr >> 11, sx = rr & 2047;
                    int hidx = cc >> 6, hd = cc & 63;
                    size_t off = (((size_t)(bb2 * HH + hidx)) * SS + sx) * HDIM + hd;
                    if (seg == 0) {
                        // q scaled by 1/sqrt(64) * log2(e) for log2-domain softmax
                        *(__half2*)(H1 + off) =
                            __floats2half2_rn(v0 * 0.180336879f, v1 * 0.180336879f);
                    } else if (seg == 1) {
                        float2 o; o.x = v0; o.y = v1;
                        *(float2*)(C + off) = o;
                        *(__half2*)(H3 + off) = __floats2half2_rn(v0, v1);
                    } else {
                        float2 o; o.x = v0; o.y = v1;
                        *(float2*)(C2 + off) = o;
                        *(__half2*)(H5 + off) = __floats2half2_rn(v0, v1);
                    }
                } else if (EPI == EPI_GELU) {
                    v0 = gelu_exact(v0); v1 = gelu_exact(v1);
                    *(__half2*)(H1 + (size_t)rr * N + col) = __floats2half2_rn(v0, v1);
                } else {
                    size_t off = (size_t)rr * N + col;
                    float2 rv = *(const float2*)(R + off);
                    float2 o; o.x = v0 + rv.x; o.y = v1 + rv.y;
                    *(float2*)(C + off) = o;
                }
            }
}

// ---------------- flash attention: fp16 QK, KV tiles processed in pairs ----------------
#define QP 144
#define FQ_B (128 * QP)           /* 18432 */
#define FKV_B (64 * QP)           /* 9216  */
#define FT_B  (2 * FKV_B)         /* one tile: K + V = 18432 */
#define FSLOT (2 * FT_B)          /* one slot: two tiles = 36864 */
#define FSMEM (FQ_B + 2 * FSLOT)  /* 92160; x2 blocks = 184320 < 228KB */

__global__ __launch_bounds__(256, 2)
void flash_tc(const __half* __restrict__ qh, const __half* __restrict__ kh,
              const __half* __restrict__ vv, __half* __restrict__ cx)
{
    extern __shared__ __align__(1024) char smem[];
    const uint32_t sb = smem_u32(smem);
    const int bh = blockIdx.y;
    const int b = bh >> 4, h = bh & 15;
    const int tid = threadIdx.x, wid = tid >> 5, l = tid & 31;

    const uint32_t aoff = (uint32_t)((l & 15) * QP + (l >> 4) * 16);
    const uint32_t boff = (uint32_t)(((l & 7) + (l >> 4) * 8) * QP + ((l >> 3) & 1) * 16);
    const uint32_t voff = (uint32_t)(((l & 7) + ((l >> 3) & 1) * 8) * QP + (l >> 4) * 16);

    #pragma unroll 1
    for (int tt = 0; tt < 2; ++tt) {
        const int qt = tt == 0 ? (int)blockIdx.x : 15 - (int)blockIdx.x;
        const int q0 = qt * 128;

        const __half* qhb = qh + ((size_t)bh * SS + q0) * HDIM;
        #pragma unroll
        for (int i = 0; i < 4; ++i) {
            int idx = tid + i * 256;
            int r = idx >> 3, c = idx & 7;
            cp16(sb + (uint32_t)(r * QP + c * 16), qhb + r * 64 + c * 8);
        }
        CP_COMMIT();

        const int npair = qt + 1;   // pairs of 64-row KV tiles
        auto ld_pair = [&](int p) {
            uint32_t dstb = sb + FQ_B + (uint32_t)((p & 1) * FSLOT);
            #pragma unroll
            for (int t2 = 0; t2 < 2; ++t2) {
                const __half* kbp = kh + ((size_t)bh * SS + (2*p + t2) * 64) * HDIM;
                const __half* vbp = vv + ((size_t)bh * SS + (2*p + t2) * 64) * HDIM;
                uint32_t db = dstb + (uint32_t)(t2 * FT_B);
                #pragma unroll
                for (int i = 0; i < 2; ++i) {
                    int idx = tid + i * 256;
                    int r = idx >> 3, c = idx & 7;
                    uint32_t so = (uint32_t)(r * QP + c * 16);
                    cp16(db + so,         kbp + r * 64 + c * 8);
                    cp16(db + FKV_B + so, vbp + r * 64 + c * 8);
                }
            }
        };
        ld_pair(0); CP_COMMIT();

        float m2[2] = {-1e30f, -1e30f}, l2[2] = {0.f, 0.f};
        float O[8][4];
        #pragma unroll
        for (int j = 0; j < 8; ++j)
            #pragma unroll
            for (int q = 0; q < 4; ++q) O[j][q] = 0.f;

        for (int p = 0; p < npair; ++p) {
            CP_WAIT(0);
            __syncthreads();
            if (p + 1 < npair) { ld_pair(p + 1); CP_COMMIT(); }

            #pragma unroll 1
            for (int t2 = 0; t2 < 2; ++t2) {
                const int kt = 2 * p + t2;
                uint32_t kb = sb + FQ_B + (uint32_t)((p & 1) * FSLOT + t2 * FT_B);
                float S[8][4];
                #pragma unroll
                for (int j = 0; j < 8; ++j)
                    #pragma unroll
                    for (int q = 0; q < 4; ++q) S[j][q] = 0.f;

                #pragma unroll
                for (int ks = 0; ks < 4; ++ks) {
                    uint32_t kadd = (uint32_t)(ks * 32);
                    uint32_t aH[4];
                    ldsm4(aH, sb + (uint32_t)(wid * 16 * QP) + aoff + kadd);
                    #pragma unroll
                    for (int jp = 0; jp < 4; ++jp) {
                        uint32_t rH[4];
                        ldsm4(rH, kb + (uint32_t)(jp * 16 * QP) + boff + kadd);
                        uint32_t bH0[2] = {rH[0], rH[1]}, bH1[2] = {rH[2], rH[3]};
                        mma16816(S[jp*2+0], aH, bH0);
                        mma16816(S[jp*2+1], aH, bH1);
                    }
                }

                if (kt * 64 + 63 > q0 + wid * 16) {
                    int rowb = q0 + wid * 16 + (l >> 2);
                    int colb = kt * 64 + 2 * (l & 3);
                    #pragma unroll
                    for (int j = 0; j < 8; ++j)
                        #pragma unroll
                        for (int q = 0; q < 4; ++q) {
                            int row = rowb + (q >> 1) * 8;
                            int col = colb + 8 * j + (q & 1);
                            if (col > row) S[j][q] = -3.0e38f;
                        }
                }

                #pragma unroll
                for (int h2 = 0; h2 < 2; ++h2) {
                    float rm = -3.4e38f;
                    #pragma unroll
                    for (int j = 0; j < 8; ++j)
                        rm = fmaxf(rm, fmaxf(S[j][h2*2], S[j][h2*2+1]));
                    rm = fmaxf(rm, __shfl_xor_sync(0xffffffffu, rm, 1));
                    rm = fmaxf(rm, __shfl_xor_sync(0xffffffffu, rm, 2));
                    float mn = fmaxf(m2[h2], rm);
                    float sc = fexp2(m2[h2] - mn);
                    float rs = 0.f;
                    #pragma unroll
                    for (int j = 0; j < 8; ++j) {
                        float p0 = fexp2(S[j][h2*2]   - mn);
                        float p1 = fexp2(S[j][h2*2+1] - mn);
                        S[j][h2*2] = p0; S[j][h2*2+1] = p1;
                        rs += p0 + p1;
                    }
                    rs += __shfl_xor_sync(0xffffffffu, rs, 1);
                    rs += __shfl_xor_sync(0xffffffffu, rs, 2);
                    l2[h2] = l2[h2] * sc + rs;
                    m2[h2] = mn;
                    #pragma unroll
                    for (int j = 0; j < 8; ++j) {
                        O[j][h2*2] *= sc; O[j][h2*2+1] *= sc;
                    }
                }

                #pragma unroll
                for (int t = 0; t < 4; ++t) {
                    uint32_t aP[4];
                    aP[0] = h2u(__floats2half2_rn(S[2*t][0],   S[2*t][1]));
                    aP[1] = h2u(__floats2half2_rn(S[2*t][2],   S[2*t][3]));
                    aP[2] = h2u(__floats2half2_rn(S[2*t+1][0], S[2*t+1][1]));
                    aP[3] = h2u(__floats2half2_rn(S[2*t+1][2], S[2*t+1][3]));
                    #pragma unroll
                    for (int jp = 0; jp < 4; ++jp) {
                        uint32_t rV[4];
                        ldsm4t(rV, kb + FKV_B + (uint32_t)(t * 16 * QP) + voff + (uint32_t)(jp * 32));
                        uint32_t b0[2] = {rV[0], rV[1]}, b1[2] = {rV[2], rV[3]};
                        mma16816(O[jp*2+0], aP, b0);
                        mma16816(O[jp*2+1], aP, b1);
                    }
                }
            }
        }

        #pragma unroll
        for (int h2 = 0; h2 < 2; ++h2) {
            float inv = 1.0f / l2[h2];
            int row = q0 + wid * 16 + (l >> 2) + h2 * 8;
            size_t base = ((size_t)b * SS + row) * DDIM + h * HDIM + 2 * (l & 3);
            #pragma unroll
            for (int j = 0; j < 8; ++j)
                *(__half2*)(cx + base + 8 * j) =
                    __floats2half2_rn(O[j][h2*2] * inv, O[j][h2*2+1] * inv);
        }
        __syncthreads();   // guard Q buffer overwrite by next tt iteration
    }
}

// ---------------- launch ----------------
extern "C" void kernel_launch(void* const* d_in, const int* in_sizes, int n_in,
                              void* d_out, int out_size)
{
    const float* x    = (const float*)d_in[0];
    const float* ln1g = (const float*)d_in[2];
    const float* ln1b = (const float*)d_in[3];
    const float* Wq   = (const float*)d_in[4];
    const float* Wk   = (const float*)d_in[5];
    const float* Wv   = (const float*)d_in[6];
    const float* Wo   = (const float*)d_in[7];
    const float* ln2g = (const float*)d_in[8];
    const float* ln2b = (const float*)d_in[9];
    const float* W1   = (const float*)d_in[10];
    const float* W2   = (const float*)d_in[11];

    float* out  = (float*)d_out;
    float* kout = out  + (size_t)MTOK * DDIM;
    float* vout = kout + (size_t)MTOK * DDIM;

    float *x2; __half *hh, *cx, *fx, *wt, *qh, *kh, *v16;
    cudaGetSymbolAddress((void**)&x2,  g_x2);
    cudaGetSymbolAddress((void**)&hh,  g_h);
    cudaGetSymbolAddress((void**)&cx,  g_cx);
    cudaGetSymbolAddress((void**)&fx,  g_f);
    cudaGetSymbolAddress((void**)&wt,  g_wt);
    cudaGetSymbolAddress((void**)&qh,  g_qh);
    cudaGetSymbolAddress((void**)&kh,  g_kh);
    cudaGetSymbolAddress((void**)&v16, g_v16);

    const size_t M1 = 1048576;
    __half *wqkv = wt, *wo = wt + 3*M1, *w1 = wt + 4*M1, *w2 = wt + 8*M1;

    cudaFuncSetAttribute(flash_tc, cudaFuncAttributeMaxDynamicSharedMemorySize, FSMEM);
    cudaFuncSetAttribute(mma_gemm<EPI_QKV>,  cudaFuncAttributeMaxDynamicSharedMemorySize, GSMEM);
    cudaFuncSetAttribute(mma_gemm<EPI_GELU>, cudaFuncAttributeMaxDynamicSharedMemorySize, GSMEM);
    cudaFuncSetAttribute(mma_gemm<EPI_RES>,  cudaFuncAttributeMaxDynamicSharedMemorySize, GSMEM);

    dim3 gQKV(3 * DDIM / 128, MTOK / 128);   // (24, 32)
    dim3 gD  (DDIM / 128, MTOK / 128);       // (8, 32)
    dim3 gF  (FF   / 128, MTOK / 128);       // (32, 32)

    wtrans_all<<<3072, 256>>>(Wq, Wk, Wv, Wo, W1, W2, wt);
    ln_k<<<MTOK, 256>>>(x, ln1g, ln1b, hh);
    mma_gemm<EPI_QKV><<<gQKV, 256, GSMEM>>>(hh, wqkv, kout, vout, qh, kh, v16, nullptr, 3*DDIM, DDIM);
    flash_tc<<<dim3(SS / 256, BB * HH), 256, FSMEM>>>(qh, kh, v16, cx);
    mma_gemm<EPI_RES><<<gD, 256, GSMEM>>>(cx, wo, x2, nullptr, nullptr, nullptr, nullptr, x, DDIM, DDIM);
    ln_k<<<MTOK, 256>>>(x2, ln2g, ln2b, hh);
    mma_gemm<EPI_GELU><<<gF, 256, GSMEM>>>(hh, w1, nullptr, nullptr, fx, nullptr, nullptr, nullptr, FF, DDIM);
    mma_gemm<EPI_RES><<<gD, 256, GSMEM>>>(fx, w2, out, nullptr, nullptr, nullptr, nullptr, x2, DDIM, FF);
}

// round 16
// speedup vs baseline: 1.0496x; 1.0034x over previous
#include <cuda_runtime.h>
#include <cuda_fp16.h>
#include <math.h>
#include <stdint.h>

#define BB 2
#define SS 2048
#define DDIM 1024
#define HH 16
#define HDIM 64
#define FF 4096
#define MTOK (BB*SS)

// ---------------- scratch ----------------
__device__ __align__(128) float  g_x2 [MTOK*DDIM];
__device__ __align__(128) __half g_h  [MTOK*DDIM];
__device__ __align__(128) __half g_cx [MTOK*DDIM];
__device__ __align__(128) __half g_f  [MTOK*FF];
__device__ __align__(128) __half g_qh [MTOK*DDIM];
__device__ __align__(128) __half g_kh [MTOK*DDIM];
__device__ __align__(128) __half g_v16[MTOK*DDIM];
#define WT_TOTAL 12582912
__device__ __align__(128) __half g_wt [WT_TOTAL];

// ---------------- helpers ----------------
__device__ __forceinline__ uint32_t smem_u32(const void* p) {
    uint32_t a;
    asm("{ .reg .u64 t; cvta.to.shared.u64 t, %1; cvt.u32.u64 %0, t; }" : "=r"(a) : "l"(p));
    return a;
}
__device__ __forceinline__ uint32_t h2u(__half2 v) {
    uint32_t r;
    memcpy(&r, &v, 4);
    return r;
}
__device__ __forceinline__ void cp16(uint32_t dst, const void* src) {
    asm volatile("cp.async.cg.shared.global [%0], [%1], 16;" :: "r"(dst), "l"(src) : "memory");
}
#define CP_COMMIT() asm volatile("cp.async.commit_group;" ::: "memory")
#define CP_WAIT(n)  asm volatile("cp.async.wait_group %0;" :: "n"(n) : "memory")

__device__ __forceinline__ void ldsm4(uint32_t* r, uint32_t addr) {
    asm volatile("ldmatrix.sync.aligned.m8n8.x4.shared.b16 {%0,%1,%2,%3}, [%4];"
        : "=r"(r[0]), "=r"(r[1]), "=r"(r[2]), "=r"(r[3]) : "r"(addr));
}
__device__ __forceinline__ void ldsm4t(uint32_t* r, uint32_t addr) {
    asm volatile("ldmatrix.sync.aligned.m8n8.x4.trans.shared.b16 {%0,%1,%2,%3}, [%4];"
        : "=r"(r[0]), "=r"(r[1]), "=r"(r[2]), "=r"(r[3]) : "r"(addr));
}
__device__ __forceinline__ void mma16816(float* c, const uint32_t* a, const uint32_t* b) {
    asm volatile("mma.sync.aligned.m16n8k16.row.col.f32.f16.f16.f32 "
        "{%0,%1,%2,%3}, {%4,%5,%6,%7}, {%8,%9}, {%0,%1,%2,%3};"
        : "+f"(c[0]), "+f"(c[1]), "+f"(c[2]), "+f"(c[3])
        : "r"(a[0]), "r"(a[1]), "r"(a[2]), "r"(a[3]), "r"(b[0]), "r"(b[1]));
}
__device__ __forceinline__ float gelu_exact(float x) {
    return 0.5f * x * (1.0f + erff(x * 0.70710678118654752f));
}
// fast exp2 (log2-domain input), degree-4, rel err ~4e-5; x <= 0 only.
__device__ __forceinline__ float fexp2(float t0) {
    float t = fmaxf(t0, -126.0f);
    float k = t + 12582912.0f;
    int   n = __float_as_int(k) - 0x4B400000;
    float g = (t - (k - 12582912.0f)) * 0.693147180559945f;
    float p = 4.1666667e-2f;
    p = fmaf(p, g, 1.6666667e-1f);
    p = fmaf(p, g, 5.0e-1f);
    p = fmaf(p, g, 1.0f);
    p = fmaf(p, g, 1.0f);
    return p * __int_as_float((n + 127) << 23);
}

// ---------------- LayerNorm -> fp16 ----------------
__global__ __launch_bounds__(256)
void ln_k(const float* __restrict__ x, const float* __restrict__ gg,
          const float* __restrict__ bb, __half* __restrict__ oh)
{
    __shared__ float red[32];
    int row = blockIdx.x, tid = threadIdx.x;
    float4 v = *(const float4*)(x + (size_t)row * DDIM + tid * 4);
    float s = v.x + v.y + v.z + v.w;
    float s2 = v.x*v.x + v.y*v.y + v.z*v.z + v.w*v.w;
    #pragma unroll
    for (int off = 16; off; off >>= 1) {
        s  += __shfl_xor_sync(0xffffffffu, s,  off);
        s2 += __shfl_xor_sync(0xffffffffu, s2, off);
    }
    int warp = tid >> 5, lane = tid & 31;
    if (lane == 0) { red[warp] = s; red[warp + 8] = s2; }
    __syncthreads();
    if (tid == 0) {
        float ts = 0.f, ts2 = 0.f;
        #pragma unroll
        for (int w = 0; w < 8; ++w) { ts += red[w]; ts2 += red[w + 8]; }
        red[16] = ts; red[17] = ts2;
    }
    __syncthreads();
    float mean = red[16] * (1.0f / DDIM);
    float var  = red[17] * (1.0f / DDIM) - mean * mean;
    float inv  = rsqrtf(var + 1e-5f);
    float4 gv = *(const float4*)(gg + tid * 4);
    float4 bv = *(const float4*)(bb + tid * 4);
    float o0 = (v.x-mean)*inv*gv.x + bv.x, o1 = (v.y-mean)*inv*gv.y + bv.y;
    float o2 = (v.z-mean)*inv*gv.z + bv.z, o3 = (v.w-mean)*inv*gv.w + bv.w;
    size_t off = (size_t)row * DDIM + tid * 4;
    ((__half2*)(oh+off))[0] = __floats2half2_rn(o0, o1);
    ((__half2*)(oh+off))[1] = __floats2half2_rn(o2, o3);
}

// ---------------- merged weight transpose ----------------
__global__ __launch_bounds__(256)
void wtrans_all(const float* __restrict__ Wq, const float* __restrict__ Wk,
                const float* __restrict__ Wv, const float* __restrict__ Wo,
                const float* __restrict__ W1, const float* __restrict__ W2,
                __half* __restrict__ wt)
{
    __shared__ __half sh[64][65];
    int bid = blockIdx.x, tid = threadIdx.x;
    const float* W; __half* T; int K, N, t;
    if (bid < 1024) {
        int seg = bid >> 8; t = bid & 255;
        W = seg == 0 ? Wq : seg == 1 ? Wk : seg == 2 ? Wv : Wo;
        T = wt + (size_t)seg * 1048576; K = 1024; N = 1024;
    } else if (bid < 2048) {
        t = bid - 1024; W = W1; T = wt + (size_t)4 * 1048576; K = 1024; N = 4096;
    } else {
        t = bid - 2048; W = W2; T = wt + (size_t)8 * 1048576; K = 4096; N = 1024;
    }
    int nt = N >> 6;
    int n0 = (t % nt) * 64, k0 = (t / nt) * 64;
    for (int idx = tid; idx < 4096; idx += 256) {
        int i = idx >> 6, j = idx & 63;
        sh[i][j] = __float2half_rn(W[(size_t)(k0 + i) * N + n0 + j]);
    }
    __syncthreads();
    for (int idx = tid; idx < 4096; idx += 256) {
        int n = idx >> 6, k = idx & 63;
        T[(size_t)(n0 + n) * K + k0 + k] = sh[k][n];
    }
}

// ---------------- fp16 mma GEMM 128x128, k32 x 4-stage (R13 proven) ----------------
#define EPI_QKV  0
#define EPI_GELU 2
#define EPI_RES  3
#define PITCH 80
#define ARR_B (128 * PITCH)
#define STG_B (2 * ARR_B)
#define GSMEM (4 * STG_B)

template<int EPI>
__global__ __launch_bounds__(256, 2)
void mma_gemm(const __half* __restrict__ A, const __half* __restrict__ B,
              float* __restrict__ C, float* __restrict__ C2,
              __half* __restrict__ H1, __half* __restrict__ H3, __half* __restrict__ H5,
              const float* __restrict__ R, int N, int K)
{
    extern __shared__ __align__(1024) char smem[];
    const uint32_t sbase = smem_u32(smem);
    const int tid = threadIdx.x, wid = tid >> 5, l = tid & 31;
    const int m0 = blockIdx.y * 128, n0 = blockIdx.x * 128;
    const int wm = wid >> 1, wn = wid & 1;

    const uint32_t aoff = (uint32_t)((l & 15) * PITCH + (l >> 4) * 16);
    const uint32_t boff = (uint32_t)(((l & 7) + (l >> 4) * 8) * PITCH + ((l >> 3) & 1) * 16);

    float acc[2][8][4];
    #pragma unroll
    for (int i = 0; i < 2; ++i)
        #pragma unroll
        for (int j = 0; j < 8; ++j)
            #pragma unroll
            for (int q = 0; q < 4; ++q) acc[i][j][q] = 0.f;

    const int T = K >> 5;

    auto ld_stage = [&](int s) {
        uint32_t dst = sbase + (uint32_t)((s & 3) * STG_B);
        int ko = s * 32;
        #pragma unroll
        for (int q = 0; q < 2; ++q) {
            int i = tid + q * 256;
            int rr = i >> 2, c = i & 3;
            uint32_t so = dst + (uint32_t)(rr * PITCH + c * 16);
            cp16(so,         A + (size_t)(m0 + rr) * K + ko + c * 8);
            cp16(so + ARR_B, B + (size_t)(n0 + rr) * K + ko + c * 8);
        }
    };

    ld_stage(0); CP_COMMIT();
    ld_stage(1); CP_COMMIT();
    ld_stage(2); CP_COMMIT();

    for (int s = 0; s < T; ++s) {
        CP_WAIT(2);
        __syncthreads();
        uint32_t buf = sbase + (uint32_t)((s & 3) * STG_B);
        #pragma unroll
        for (int kk = 0; kk < 2; ++kk) {
            uint32_t kb = (uint32_t)(kk * 32);
            uint32_t ah[2][4], bh[8][2];
            #pragma unroll
            for (int i = 0; i < 2; ++i)
                ldsm4(ah[i], buf + (uint32_t)((wm * 32 + i * 16) * PITCH) + aoff + kb);
            #pragma unroll
            for (int jp = 0; jp < 4; ++jp) {
                uint32_t rh[4];
                ldsm4(rh, buf + ARR_B + (uint32_t)((wn * 64 + jp * 16) * PITCH) + boff + kb);
                bh[jp*2+0][0] = rh[0]; bh[jp*2+0][1] = rh[1];
                bh[jp*2+1][0] = rh[2]; bh[jp*2+1][1] = rh[3];
            }
            #pragma unroll
            for (int i = 0; i < 2; ++i)
                #pragma unroll
                for (int j = 0; j < 8; ++j)
                    mma16816(acc[i][j], ah[i], bh[j]);
        }
        if (s + 3 < T) ld_stage(s + 3);
        CP_COMMIT();
    }

    #pragma unroll
    for (int i = 0; i < 2; ++i)
        #pragma unroll
        for (int j = 0; j < 8; ++j)
            #pragma unroll
            for (int h2 = 0; h2 < 2; ++h2) {
                int rr = m0 + wm * 32 + i * 16 + (l >> 2) + h2 * 8;
                int col = n0 + wn * 64 + j * 8 + (l & 3) * 2;
                float v0 = acc[i][j][h2 * 2 + 0];
                float v1 = acc[i][j][h2 * 2 + 1];
                if (EPI == EPI_QKV) {
                    int seg = col >> 10, cc = col & 1023;
                    int bb2 = rr >> 11, sx = rr & 2047;
                    int hidx = cc >> 6, hd = cc & 63;
                    size_t off = (((size_t)(bb2 * HH + hidx)) * SS + sx) * HDIM + hd;
                    if (seg == 0) {
                        // q scaled by 1/sqrt(64) * log2(e) for log2-domain softmax
                        *(__half2*)(H1 + off) =
                            __floats2half2_rn(v0 * 0.180336879f, v1 * 0.180336879f);
                    } else if (seg == 1) {
                        float2 o; o.x = v0; o.y = v1;
                        *(float2*)(C + off) = o;
                        *(__half2*)(H3 + off) = __floats2half2_rn(v0, v1);
                    } else {
                        float2 o; o.x = v0; o.y = v1;
                        *(float2*)(C2 + off) = o;
                        *(__half2*)(H5 + off) = __floats2half2_rn(v0, v1);
                    }
                } else if (EPI == EPI_GELU) {
                    v0 = gelu_exact(v0); v1 = gelu_exact(v1);
                    *(__half2*)(H1 + (size_t)rr * N + col) = __floats2half2_rn(v0, v1);
                } else {
                    size_t off = (size_t)rr * N + col;
                    float2 rv = *(const float2*)(R + off);
                    float2 o; o.x = v0 + rv.x; o.y = v1 + rv.y;
                    *(float2*)(C + off) = o;
                }
            }
}

// ---------------- flash attention: Q in registers, paired KV tiles ----------------
#define QP 144
#define FQ_B (128 * QP)
#define FKV_B (64 * QP)
#define FT_B  (2 * FKV_B)
#define FSLOT (2 * FT_B)
#define FSMEM (FQ_B + 2 * FSLOT)   /* 92160 */

__global__ __launch_bounds__(256, 2)
void flash_tc(const __half* __restrict__ qh, const __half* __restrict__ kh,
              const __half* __restrict__ vv, __half* __restrict__ cx)
{
    extern __shared__ __align__(1024) char smem[];
    const uint32_t sb = smem_u32(smem);
    const int bh = blockIdx.y;
    const int b = bh >> 4, h = bh & 15;
    const int tid = threadIdx.x, wid = tid >> 5, l = tid & 31;

    const uint32_t aoff = (uint32_t)((l & 15) * QP + (l >> 4) * 16);
    const uint32_t boff = (uint32_t)(((l & 7) + (l >> 4) * 8) * QP + ((l >> 3) & 1) * 16);
    const uint32_t voff = (uint32_t)(((l & 7) + ((l >> 3) & 1) * 8) * QP + (l >> 4) * 16);

    #pragma unroll 1
    for (int tt = 0; tt < 2; ++tt) {
        const int qt = tt == 0 ? (int)blockIdx.x : 15 - (int)blockIdx.x;
        const int q0 = qt * 128;

        const __half* qhb = qh + ((size_t)bh * SS + q0) * HDIM;
        #pragma unroll
        for (int i = 0; i < 4; ++i) {
            int idx = tid + i * 256;
            int r = idx >> 3, c = idx & 7;
            cp16(sb + (uint32_t)(r * QP + c * 16), qhb + r * 64 + c * 8);
        }
        CP_COMMIT();

        const int npair = qt + 1;
        auto ld_pair = [&](int p) {
            uint32_t dstb = sb + FQ_B + (uint32_t)((p & 1) * FSLOT);
            #pragma unroll
            for (int t2 = 0; t2 < 2; ++t2) {
                const __half* kbp = kh + ((size_t)bh * SS + (2*p + t2) * 64) * HDIM;
                const __half* vbp = vv + ((size_t)bh * SS + (2*p + t2) * 64) * HDIM;
                uint32_t db = dstb + (uint32_t)(t2 * FT_B);
                #pragma unroll
                for (int i = 0; i < 2; ++i) {
                    int idx = tid + i * 256;
                    int r = idx >> 3, c = idx & 7;
                    uint32_t so = (uint32_t)(r * QP + c * 16);
                    cp16(db + so,         kbp + r * 64 + c * 8);
                    cp16(db + FKV_B + so, vbp + r * 64 + c * 8);
                }
            }
        };
        ld_pair(0); CP_COMMIT();
        CP_WAIT(0);
        __syncthreads();

        // hoist: Q fragments are invariant across the whole KV loop
        uint32_t qreg[4][4];
        #pragma unroll
        for (int ks = 0; ks < 4; ++ks)
            ldsm4(qreg[ks], sb + (uint32_t)(wid * 16 * QP) + aoff + (uint32_t)(ks * 32));

        float m2[2] = {-1e30f, -1e30f}, l2[2] = {0.f, 0.f};
        float O[8][4];
        #pragma unroll
        for (int j = 0; j < 8; ++j)
            #pragma unroll
            for (int q = 0; q < 4; ++q) O[j][q] = 0.f;

        for (int p = 0; p < npair; ++p) {
            if (p > 0) { CP_WAIT(0); __syncthreads(); }
            if (p + 1 < npair) { ld_pair(p + 1); CP_COMMIT(); }

            #pragma unroll 1
            for (int t2 = 0; t2 < 2; ++t2) {
                const int kt = 2 * p + t2;
                uint32_t kb = sb + FQ_B + (uint32_t)((p & 1) * FSLOT + t2 * FT_B);
                float S[8][4];
                #pragma unroll
                for (int j = 0; j < 8; ++j)
                    #pragma unroll
                    for (int q = 0; q < 4; ++q) S[j][q] = 0.f;

                #pragma unroll
                for (int ks = 0; ks < 4; ++ks) {
                    uint32_t kadd = (uint32_t)(ks * 32);
                    #pragma unroll
                    for (int jp = 0; jp < 4; ++jp) {
                        uint32_t rH[4];
                        ldsm4(rH, kb + (uint32_t)(jp * 16 * QP) + boff + kadd);
                        uint32_t bH0[2] = {rH[0], rH[1]}, bH1[2] = {rH[2], rH[3]};
                        mma16816(S[jp*2+0], qreg[ks], bH0);
                        mma16816(S[jp*2+1], qreg[ks], bH1);
                    }
                }

                if (kt * 64 + 63 > q0 + wid * 16) {
                    int rowb = q0 + wid * 16 + (l >> 2);
                    int colb = kt * 64 + 2 * (l & 3);
                    #pragma unroll
                    for (int j = 0; j < 8; ++j)
                        #pragma unroll
                        for (int q = 0; q < 4; ++q) {
                            int row = rowb + (q >> 1) * 8;
                            int col = colb + 8 * j + (q & 1);
                            if (col > row) S[j][q] = -3.0e38f;
                        }
                }

                #pragma unroll
                for (int h2 = 0; h2 < 2; ++h2) {
                    float rm = -3.4e38f;
                    #pragma unroll
                    for (int j = 0; j < 8; ++j)
                        rm = fmaxf(rm, fmaxf(S[j][h2*2], S[j][h2*2+1]));
                    rm = fmaxf(rm, __shfl_xor_sync(0xffffffffu, rm, 1));
                    rm = fmaxf(rm, __shfl_xor_sync(0xffffffffu, rm, 2));
                    if (rm > m2[h2]) {             // max changed: rescale state
                        float sc = fexp2(m2[h2] - rm);
                        l2[h2] *= sc;
                        #pragma unroll
                        for (int j = 0; j < 8; ++j) {
                            O[j][h2*2] *= sc; O[j][h2*2+1] *= sc;
                        }
                        m2[h2] = rm;
                    }
                    float mn = m2[h2];
                    float rs = 0.f;
                    #pragma unroll
                    for (int j = 0; j < 8; ++j) {
                        float p0 = fexp2(S[j][h2*2]   - mn);
                        float p1 = fexp2(S[j][h2*2+1] - mn);
                        S[j][h2*2] = p0; S[j][h2*2+1] = p1;
                        rs += p0 + p1;
                    }
                    rs += __shfl_xor_sync(0xffffffffu, rs, 1);
                    rs += __shfl_xor_sync(0xffffffffu, rs, 2);
                    l2[h2] += rs;
                }

                #pragma unroll
                for (int t = 0; t < 4; ++t) {
                    uint32_t aP[4];
                    aP[0] = h2u(__floats2half2_rn(S[2*t][0],   S[2*t][1]));
                    aP[1] = h2u(__floats2half2_rn(S[2*t][2],   S[2*t][3]));
                    aP[2] = h2u(__floats2half2_rn(S[2*t+1][0], S[2*t+1][1]));
                    aP[3] = h2u(__floats2half2_rn(S[2*t+1][2], S[2*t+1][3]));
                    #pragma unroll
                    for (int jp = 0; jp < 4; ++jp) {
                        uint32_t rV[4];
                        ldsm4t(rV, kb + FKV_B + (uint32_t)(t * 16 * QP) + voff + (uint32_t)(jp * 32));
                        uint32_t b0[2] = {rV[0], rV[1]}, b1[2] = {rV[2], rV[3]};
                        mma16816(O[jp*2+0], aP, b0);
                        mma16816(O[jp*2+1], aP, b1);
                    }
                }
            }
        }

        #pragma unroll
        for (int h2 = 0; h2 < 2; ++h2) {
            float inv = 1.0f / l2[h2];
            int row = q0 + wid * 16 + (l >> 2) + h2 * 8;
            size_t base = ((size_t)b * SS + row) * DDIM + h * HDIM + 2 * (l & 3);
            #pragma unroll
            for (int j = 0; j < 8; ++j)
                *(__half2*)(cx + base + 8 * j) =
                    __floats2half2_rn(O[j][h2*2] * inv, O[j][h2*2+1] * inv);
        }
        __syncthreads();   // guard Q buffer overwrite by next tt iteration
    }
}

// ---------------- launch ----------------
extern "C" void kernel_launch(void* const* d_in, const int* in_sizes, int n_in,
                              void* d_out, int out_size)
{
    const float* x    = (const float*)d_in[0];
    const float* ln1g = (const float*)d_in[2];
    const float* ln1b = (const float*)d_in[3];
    const float* Wq   = (const float*)d_in[4];
    const float* Wk   = (const float*)d_in[5];
    const float* Wv   = (const float*)d_in[6];
    const float* Wo   = (const float*)d_in[7];
    const float* ln2g = (const float*)d_in[8];
    const float* ln2b = (const float*)d_in[9];
    const float* W1   = (const float*)d_in[10];
    const float* W2   = (const float*)d_in[11];

    float* out  = (float*)d_out;
    float* kout = out  + (size_t)MTOK * DDIM;
    float* vout = kout + (size_t)MTOK * DDIM;

    float *x2; __half *hh, *cx, *fx, *wt, *qh, *kh, *v16;
    cudaGetSymbolAddress((void**)&x2,  g_x2);
    cudaGetSymbolAddress((void**)&hh,  g_h);
    cudaGetSymbolAddress((void**)&cx,  g_cx);
    cudaGetSymbolAddress((void**)&fx,  g_f);
    cudaGetSymbolAddress((void**)&wt,  g_wt);
    cudaGetSymbolAddress((void**)&qh,  g_qh);
    cudaGetSymbolAddress((void**)&kh,  g_kh);
    cudaGetSymbolAddress((void**)&v16, g_v16);

    const size_t M1 = 1048576;
    __half *wqkv = wt, *wo = wt + 3*M1, *w1 = wt + 4*M1, *w2 = wt + 8*M1;

    cudaFuncSetAttribute(flash_tc, cudaFuncAttributeMaxDynamicSharedMemorySize, FSMEM);
    cudaFuncSetAttribute(mma_gemm<EPI_QKV>,  cudaFuncAttributeMaxDynamicSharedMemorySize, GSMEM);
    cudaFuncSetAttribute(mma_gemm<EPI_GELU>, cudaFuncAttributeMaxDynamicSharedMemorySize, GSMEM);
    cudaFuncSetAttribute(mma_gemm<EPI_RES>,  cudaFuncAttributeMaxDynamicSharedMemorySize, GSMEM);

    dim3 gQKV(3 * DDIM / 128, MTOK / 128);   // (24, 32)
    dim3 gD  (DDIM / 128, MTOK / 128);       // (8, 32)
    dim3 gF  (FF   / 128, MTOK / 128);       // (32, 32)

    wtrans_all<<<3072, 256>>>(Wq, Wk, Wv, Wo, W1, W2, wt);
    ln_k<<<MTOK, 256>>>(x, ln1g, ln1b, hh);
    mma_gemm<EPI_QKV><<<gQKV, 256, GSMEM>>>(hh, wqkv, kout, vout, qh, kh, v16, nullptr, 3*DDIM, DDIM);
    flash_tc<<<dim3(SS / 256, BB * HH), 256, FSMEM>>>(qh, kh, v16, cx);
    mma_gemm<EPI_RES><<<gD, 256, GSMEM>>>(cx, wo, x2, nullptr, nullptr, nullptr, nullptr, x, DDIM, DDIM);
    ln_k<<<MTOK, 256>>>(x2, ln2g, ln2b, hh);
    mma_gemm<EPI_GELU><<<gF, 256, GSMEM>>>(hh, w1, nullptr, nullptr, fx, nullptr, nullptr, nullptr, FF, DDIM);
    mma_gemm<EPI_RES><<<gD, 256, GSMEM>>>(fx, w2, out, nullptr, nullptr, nullptr, nullptr, x2, DDIM, FF);
}

// round 17
// speedup vs baseline: 1.0930x; 1.0414x over previous
#include <cuda_runtime.h>
#include <cuda_fp16.h>
#include <math.h>
#include <stdint.h>

#define BB 2
#define SS 2048
#define DDIM 1024
#define HH 16
#define HDIM 64
#define FF 4096
#define MTOK (BB*SS)

// ---------------- scratch ----------------
__device__ __align__(128) float  g_x2 [MTOK*DDIM];
__device__ __align__(128) __half g_h  [MTOK*DDIM];
__device__ __align__(128) __half g_cx [MTOK*DDIM];
__device__ __align__(128) __half g_f  [MTOK*FF];
__device__ __align__(128) __half g_qh [MTOK*DDIM];
__device__ __align__(128) __half g_kh [MTOK*DDIM];
__device__ __align__(128) __half g_v16[MTOK*DDIM];
#define WT_TOTAL 12582912
__device__ __align__(128) __half g_wt [WT_TOTAL];

// ---------------- helpers ----------------
__device__ __forceinline__ uint32_t smem_u32(const void* p) {
    uint32_t a;
    asm("{ .reg .u64 t; cvta.to.shared.u64 t, %1; cvt.u32.u64 %0, t; }" : "=r"(a) : "l"(p));
    return a;
}
__device__ __forceinline__ uint32_t h2u(__half2 v) {
    uint32_t r;
    memcpy(&r, &v, 4);
    return r;
}
__device__ __forceinline__ void cp16(uint32_t dst, const void* src) {
    asm volatile("cp.async.cg.shared.global [%0], [%1], 16;" :: "r"(dst), "l"(src) : "memory");
}
#define CP_COMMIT() asm volatile("cp.async.commit_group;" ::: "memory")
#define CP_WAIT(n)  asm volatile("cp.async.wait_group %0;" :: "n"(n) : "memory")

__device__ __forceinline__ void ldsm4(uint32_t* r, uint32_t addr) {
    asm volatile("ldmatrix.sync.aligned.m8n8.x4.shared.b16 {%0,%1,%2,%3}, [%4];"
        : "=r"(r[0]), "=r"(r[1]), "=r"(r[2]), "=r"(r[3]) : "r"(addr));
}
__device__ __forceinline__ void ldsm4t(uint32_t* r, uint32_t addr) {
    asm volatile("ldmatrix.sync.aligned.m8n8.x4.trans.shared.b16 {%0,%1,%2,%3}, [%4];"
        : "=r"(r[0]), "=r"(r[1]), "=r"(r[2]), "=r"(r[3]) : "r"(addr));
}
__device__ __forceinline__ void mma16816(float* c, const uint32_t* a, const uint32_t* b) {
    asm volatile("mma.sync.aligned.m16n8k16.row.col.f32.f16.f16.f32 "
        "{%0,%1,%2,%3}, {%4,%5,%6,%7}, {%8,%9}, {%0,%1,%2,%3};"
        : "+f"(c[0]), "+f"(c[1]), "+f"(c[2]), "+f"(c[3])
        : "r"(a[0]), "r"(a[1]), "r"(a[2]), "r"(a[3]), "r"(b[0]), "r"(b[1]));
}
__device__ __forceinline__ float gelu_exact(float x) {
    return 0.5f * x * (1.0f + erff(x * 0.70710678118654752f));
}
// fast exp2 (log2-domain input), degree-4, rel err ~4e-5; x <= 0 only.
__device__ __forceinline__ float fexp2(float t0) {
    float t = fmaxf(t0, -126.0f);
    float k = t + 12582912.0f;
    int   n = __float_as_int(k) - 0x4B400000;
    float g = (t - (k - 12582912.0f)) * 0.693147180559945f;
    float p = 4.1666667e-2f;
    p = fmaf(p, g, 1.6666667e-1f);
    p = fmaf(p, g, 5.0e-1f);
    p = fmaf(p, g, 1.0f);
    p = fmaf(p, g, 1.0f);
    return p * __int_as_float((n + 127) << 23);
}

// ---------------- LayerNorm: warp-per-row, no block barriers ----------------
__global__ __launch_bounds__(256)
void ln_k(const float* __restrict__ x, const float* __restrict__ gg,
          const float* __restrict__ bb, __half* __restrict__ oh)
{
    int wid = threadIdx.x >> 5, lane = threadIdx.x & 31;
    int row = blockIdx.x * 8 + wid;
    const float* xr = x + (size_t)row * DDIM;

    float4 v[8];
    float s = 0.f, s2 = 0.f;
    #pragma unroll
    for (int i = 0; i < 8; ++i) {
        v[i] = *(const float4*)(xr + (lane + 32 * i) * 4);
        s  += v[i].x + v[i].y + v[i].z + v[i].w;
        s2 += v[i].x*v[i].x + v[i].y*v[i].y + v[i].z*v[i].z + v[i].w*v[i].w;
    }
    #pragma unroll
    for (int off = 16; off; off >>= 1) {
        s  += __shfl_xor_sync(0xffffffffu, s,  off);
        s2 += __shfl_xor_sync(0xffffffffu, s2, off);
    }
    float mean = s * (1.0f / DDIM);
    float var  = s2 * (1.0f / DDIM) - mean * mean;
    float inv  = rsqrtf(var + 1e-5f);

    #pragma unroll
    for (int i = 0; i < 8; ++i) {
        int c = (lane + 32 * i) * 4;
        float4 gv = *(const float4*)(gg + c);
        float4 bv = *(const float4*)(bb + c);
        float o0 = (v[i].x - mean) * inv * gv.x + bv.x;
        float o1 = (v[i].y - mean) * inv * gv.y + bv.y;
        float o2 = (v[i].z - mean) * inv * gv.z + bv.z;
        float o3 = (v[i].w - mean) * inv * gv.w + bv.w;
        size_t off = (size_t)row * DDIM + c;
        ((__half2*)(oh + off))[0] = __floats2half2_rn(o0, o1);
        ((__half2*)(oh + off))[1] = __floats2half2_rn(o2, o3);
    }
}

// ---------------- merged weight transpose, vectorized I/O ----------------
__global__ __launch_bounds__(256)
void wtrans_all(const float* __restrict__ Wq, const float* __restrict__ Wk,
                const float* __restrict__ Wv, const float* __restrict__ Wo,
                const float* __restrict__ W1, const float* __restrict__ W2,
                __half* __restrict__ wt)
{
    __shared__ __half sh[64][65];
    int bid = blockIdx.x, tid = threadIdx.x;
    const float* W; __half* T; int K, N, t;
    if (bid < 1024) {
        int seg = bid >> 8; t = bid & 255;
        W = seg == 0 ? Wq : seg == 1 ? Wk : seg == 2 ? Wv : Wo;
        T = wt + (size_t)seg * 1048576; K = 1024; N = 1024;
    } else if (bid < 2048) {
        t = bid - 1024; W = W1; T = wt + (size_t)4 * 1048576; K = 1024; N = 4096;
    } else {
        t = bid - 2048; W = W2; T = wt + (size_t)8 * 1048576; K = 4096; N = 1024;
    }
    int nt = N >> 6;
    int n0 = (t % nt) * 64, k0 = (t / nt) * 64;
    #pragma unroll
    for (int it = 0; it < 4; ++it) {
        int idx = tid + it * 256;            // 0..1023 float4s
        int i = idx >> 4, j4 = (idx & 15) * 4;
        float4 w = *(const float4*)(W + (size_t)(k0 + i) * N + n0 + j4);
        sh[i][j4 + 0] = __float2half_rn(w.x);
        sh[i][j4 + 1] = __float2half_rn(w.y);
        sh[i][j4 + 2] = __float2half_rn(w.z);
        sh[i][j4 + 3] = __float2half_rn(w.w);
    }
    __syncthreads();
    #pragma unroll
    for (int it = 0; it < 8; ++it) {
        int idx = tid + it * 256;            // 0..2047 half2s
        int n = idx >> 5, k2 = (idx & 31) * 2;
        __half2 val = __halves2half2(sh[k2][n], sh[k2 + 1][n]);
        *(__half2*)(T + (size_t)(n0 + n) * K + k0 + k2) = val;
    }
}

// ---------------- fp16 mma GEMM 128x128, k32 x 4-stage (R13 proven) ----------------
#define EPI_QKV  0
#define EPI_GELU 2
#define EPI_RES  3
#define PITCH 80
#define ARR_B (128 * PITCH)
#define STG_B (2 * ARR_B)
#define GSMEM (4 * STG_B)

template<int EPI>
__global__ __launch_bounds__(256, 2)
void mma_gemm(const __half* __restrict__ A, const __half* __restrict__ B,
              float* __restrict__ C, float* __restrict__ C2,
              __half* __restrict__ H1, __half* __restrict__ H3, __half* __restrict__ H5,
              const float* __restrict__ R, int N, int K)
{
    extern __shared__ __align__(1024) char smem[];
    const uint32_t sbase = smem_u32(smem);
    const int tid = threadIdx.x, wid = tid >> 5, l = tid & 31;
    const int m0 = blockIdx.y * 128, n0 = blockIdx.x * 128;
    const int wm = wid >> 1, wn = wid & 1;

    const uint32_t aoff = (uint32_t)((l & 15) * PITCH + (l >> 4) * 16);
    const uint32_t boff = (uint32_t)(((l & 7) + (l >> 4) * 8) * PITCH + ((l >> 3) & 1) * 16);

    float acc[2][8][4];
    #pragma unroll
    for (int i = 0; i < 2; ++i)
        #pragma unroll
        for (int j = 0; j < 8; ++j)
            #pragma unroll
            for (int q = 0; q < 4; ++q) acc[i][j][q] = 0.f;

    const int T = K >> 5;

    auto ld_stage = [&](int s) {
        uint32_t dst = sbase + (uint32_t)((s & 3) * STG_B);
        int ko = s * 32;
        #pragma unroll
        for (int q = 0; q < 2; ++q) {
            int i = tid + q * 256;
            int rr = i >> 2, c = i & 3;
            uint32_t so = dst + (uint32_t)(rr * PITCH + c * 16);
            cp16(so,         A + (size_t)(m0 + rr) * K + ko + c * 8);
            cp16(so + ARR_B, B + (size_t)(n0 + rr) * K + ko + c * 8);
        }
    };

    ld_stage(0); CP_COMMIT();
    ld_stage(1); CP_COMMIT();
    ld_stage(2); CP_COMMIT();

    for (int s = 0; s < T; ++s) {
        CP_WAIT(2);
        __syncthreads();
        uint32_t buf = sbase + (uint32_t)((s & 3) * STG_B);
        #pragma unroll
        for (int kk = 0; kk < 2; ++kk) {
            uint32_t kb = (uint32_t)(kk * 32);
            uint32_t ah[2][4], bh[8][2];
            #pragma unroll
            for (int i = 0; i < 2; ++i)
                ldsm4(ah[i], buf + (uint32_t)((wm * 32 + i * 16) * PITCH) + aoff + kb);
            #pragma unroll
            for (int jp = 0; jp < 4; ++jp) {
                uint32_t rh[4];
                ldsm4(rh, buf + ARR_B + (uint32_t)((wn * 64 + jp * 16) * PITCH) + boff + kb);
                bh[jp*2+0][0] = rh[0]; bh[jp*2+0][1] = rh[1];
                bh[jp*2+1][0] = rh[2]; bh[jp*2+1][1] = rh[3];
            }
            #pragma unroll
            for (int i = 0; i < 2; ++i)
                #pragma unroll
                for (int j = 0; j < 8; ++j)
                    mma16816(acc[i][j], ah[i], bh[j]);
        }
        if (s + 3 < T) ld_stage(s + 3);
        CP_COMMIT();
    }

    #pragma unroll
    for (int i = 0; i < 2; ++i)
        #pragma unroll
        for (int j = 0; j < 8; ++j)
            #pragma unroll
            for (int h2 = 0; h2 < 2; ++h2) {
                int rr = m0 + wm * 32 + i * 16 + (l >> 2) + h2 * 8;
                int col = n0 + wn * 64 + j * 8 + (l & 3) * 2;
                float v0 = acc[i][j][h2 * 2 + 0];
                float v1 = acc[i][j][h2 * 2 + 1];
                if (EPI == EPI_QKV) {
                    int seg = col >> 10, cc = col & 1023;
                    int bb2 = rr >> 11, sx = rr & 2047;
                    int hidx = cc >> 6, hd = cc & 63;
                    size_t off = (((size_t)(bb2 * HH + hidx)) * SS + sx) * HDIM + hd;
                    if (seg == 0) {
                        *(__half2*)(H1 + off) =
                            __floats2half2_rn(v0 * 0.180336879f, v1 * 0.180336879f);
                    } else if (seg == 1) {
                        float2 o; o.x = v0; o.y = v1;
                        *(float2*)(C + off) = o;
                        *(__half2*)(H3 + off) = __floats2half2_rn(v0, v1);
                    } else {
                        float2 o; o.x = v0; o.y = v1;
                        *(float2*)(C2 + off) = o;
                        *(__half2*)(H5 + off) = __floats2half2_rn(v0, v1);
                    }
                } else if (EPI == EPI_GELU) {
                    v0 = gelu_exact(v0); v1 = gelu_exact(v1);
                    *(__half2*)(H1 + (size_t)rr * N + col) = __floats2half2_rn(v0, v1);
                } else {
                    size_t off = (size_t)rr * N + col;
                    float2 rv = *(const float2*)(R + off);
                    float2 o; o.x = v0 + rv.x; o.y = v1 + rv.y;
                    *(float2*)(C + off) = o;
                }
            }
}

// ---------------- flash attention: Q in registers, paired KV tiles ----------------
#define QP 144
#define FQ_B (128 * QP)
#define FKV_B (64 * QP)
#define FT_B  (2 * FKV_B)
#define FSLOT (2 * FT_B)
#define FSMEM (FQ_B + 2 * FSLOT)

__global__ __launch_bounds__(256, 2)
void flash_tc(const __half* __restrict__ qh, const __half* __restrict__ kh,
              const __half* __restrict__ vv, __half* __restrict__ cx)
{
    extern __shared__ __align__(1024) char smem[];
    const uint32_t sb = smem_u32(smem);
    const int bh = blockIdx.y;
    const int b = bh >> 4, h = bh & 15;
    const int tid = threadIdx.x, wid = tid >> 5, l = tid & 31;

    const uint32_t aoff = (uint32_t)((l & 15) * QP + (l >> 4) * 16);
    const uint32_t boff = (uint32_t)(((l & 7) + (l >> 4) * 8) * QP + ((l >> 3) & 1) * 16);
    const uint32_t voff = (uint32_t)(((l & 7) + ((l >> 3) & 1) * 8) * QP + (l >> 4) * 16);

    #pragma unroll 1
    for (int tt = 0; tt < 2; ++tt) {
        const int qt = tt == 0 ? (int)blockIdx.x : 15 - (int)blockIdx.x;
        const int q0 = qt * 128;

        const __half* qhb = qh + ((size_t)bh * SS + q0) * HDIM;
        #pragma unroll
        for (int i = 0; i < 4; ++i) {
            int idx = tid + i * 256;
            int r = idx >> 3, c = idx & 7;
            cp16(sb + (uint32_t)(r * QP + c * 16), qhb + r * 64 + c * 8);
        }
        CP_COMMIT();

        const int npair = qt + 1;
        auto ld_pair = [&](int p) {
            uint32_t dstb = sb + FQ_B + (uint32_t)((p & 1) * FSLOT);
            #pragma unroll
            for (int t2 = 0; t2 < 2; ++t2) {
                const __half* kbp = kh + ((size_t)bh * SS + (2*p + t2) * 64) * HDIM;
                const __half* vbp = vv + ((size_t)bh * SS + (2*p + t2) * 64) * HDIM;
                uint32_t db = dstb + (uint32_t)(t2 * FT_B);
                #pragma unroll
                for (int i = 0; i < 2; ++i) {
                    int idx = tid + i * 256;
                    int r = idx >> 3, c = idx & 7;
                    uint32_t so = (uint32_t)(r * QP + c * 16);
                    cp16(db + so,         kbp + r * 64 + c * 8);
                    cp16(db + FKV_B + so, vbp + r * 64 + c * 8);
                }
            }
        };
        ld_pair(0); CP_COMMIT();
        CP_WAIT(0);
        __syncthreads();

        uint32_t qreg[4][4];
        #pragma unroll
        for (int ks = 0; ks < 4; ++ks)
            ldsm4(qreg[ks], sb + (uint32_t)(wid * 16 * QP) + aoff + (uint32_t)(ks * 32));

        float m2[2] = {-1e30f, -1e30f}, l2[2] = {0.f, 0.f};
        float O[8][4];
        #pragma unroll
        for (int j = 0; j < 8; ++j)
            #pragma unroll
            for (int q = 0; q < 4; ++q) O[j][q] = 0.f;

        for (int p = 0; p < npair; ++p) {
            if (p > 0) { CP_WAIT(0); __syncthreads(); }
            if (p + 1 < npair) { ld_pair(p + 1); CP_COMMIT(); }

            #pragma unroll 1
            for (int t2 = 0; t2 < 2; ++t2) {
                const int kt = 2 * p + t2;
                uint32_t kb = sb + FQ_B + (uint32_t)((p & 1) * FSLOT + t2 * FT_B);
                float S[8][4];
                #pragma unroll
                for (int j = 0; j < 8; ++j)
                    #pragma unroll
                    for (int q = 0; q < 4; ++q) S[j][q] = 0.f;

                #pragma unroll
                for (int ks = 0; ks < 4; ++ks) {
                    uint32_t kadd = (uint32_t)(ks * 32);
                    #pragma unroll
                    for (int jp = 0; jp < 4; ++jp) {
                        uint32_t rH[4];
                        ldsm4(rH, kb + (uint32_t)(jp * 16 * QP) + boff + kadd);
                        uint32_t bH0[2] = {rH[0], rH[1]}, bH1[2] = {rH[2], rH[3]};
                        mma16816(S[jp*2+0], qreg[ks], bH0);
                        mma16816(S[jp*2+1], qreg[ks], bH1);
                    }
                }

                if (kt * 64 + 63 > q0 + wid * 16) {
                    int rowb = q0 + wid * 16 + (l >> 2);
                    int colb = kt * 64 + 2 * (l & 3);
                    #pragma unroll
                    for (int j = 0; j < 8; ++j)
                        #pragma unroll
                        for (int q = 0; q < 4; ++q) {
                            int row = rowb + (q >> 1) * 8;
                            int col = colb + 8 * j + (q & 1);
                            if (col > row) S[j][q] = -3.0e38f;
                        }
                }

                #pragma unroll
                for (int h2 = 0; h2 < 2; ++h2) {
                    float rm = -3.4e38f;
                    #pragma unroll
                    for (int j = 0; j < 8; ++j)
                        rm = fmaxf(rm, fmaxf(S[j][h2*2], S[j][h2*2+1]));
                    rm = fmaxf(rm, __shfl_xor_sync(0xffffffffu, rm, 1));
                    rm = fmaxf(rm, __shfl_xor_sync(0xffffffffu, rm, 2));
                    if (rm > m2[h2]) {
                        float sc = fexp2(m2[h2] - rm);
                        l2[h2] *= sc;
                        #pragma unroll
                        for (int j = 0; j < 8; ++j) {
                            O[j][h2*2] *= sc; O[j][h2*2+1] *= sc;
                        }
                        m2[h2] = rm;
                    }
                    float mn = m2[h2];
                    float rs = 0.f;
                    #pragma unroll
                    for (int j = 0; j < 8; ++j) {
                        float p0 = fexp2(S[j][h2*2]   - mn);
                        float p1 = fexp2(S[j][h2*2+1] - mn);
                        S[j][h2*2] = p0; S[j][h2*2+1] = p1;
                        rs += p0 + p1;
                    }
                    rs += __shfl_xor_sync(0xffffffffu, rs, 1);
                    rs += __shfl_xor_sync(0xffffffffu, rs, 2);
                    l2[h2] += rs;
                }

                #pragma unroll
                for (int t = 0; t < 4; ++t) {
                    uint32_t aP[4];
                    aP[0] = h2u(__floats2half2_rn(S[2*t][0],   S[2*t][1]));
                    aP[1] = h2u(__floats2half2_rn(S[2*t][2],   S[2*t][3]));
                    aP[2] = h2u(__floats2half2_rn(S[2*t+1][0], S[2*t+1][1]));
                    aP[3] = h2u(__floats2half2_rn(S[2*t+1][2], S[2*t+1][3]));
                    #pragma unroll
                    for (int jp = 0; jp < 4; ++jp) {
                        uint32_t rV[4];
                        ldsm4t(rV, kb + FKV_B + (uint32_t)(t * 16 * QP) + voff + (uint32_t)(jp * 32));
                        uint32_t b0[2] = {rV[0], rV[1]}, b1[2] = {rV[2], rV[3]};
                        mma16816(O[jp*2+0], aP, b0);
                        mma16816(O[jp*2+1], aP, b1);
                    }
                }
            }
        }

        #pragma unroll
        for (int h2 = 0; h2 < 2; ++h2) {
            float inv = 1.0f / l2[h2];
            int row = q0 + wid * 16 + (l >> 2) + h2 * 8;
            size_t base = ((size_t)b * SS + row) * DDIM + h * HDIM + 2 * (l & 3);
            #pragma unroll
            for (int j = 0; j < 8; ++j)
                *(__half2*)(cx + base + 8 * j) =
                    __floats2half2_rn(O[j][h2*2] * inv, O[j][h2*2+1] * inv);
        }
        __syncthreads();
    }
}

// ---------------- launch ----------------
extern "C" void kernel_launch(void* const* d_in, const int* in_sizes, int n_in,
                              void* d_out, int out_size)
{
    const float* x    = (const float*)d_in[0];
    const float* ln1g = (const float*)d_in[2];
    const float* ln1b = (const float*)d_in[3];
    const float* Wq   = (const float*)d_in[4];
    const float* Wk   = (const float*)d_in[5];
    const float* Wv   = (const float*)d_in[6];
    const float* Wo   = (const float*)d_in[7];
    const float* ln2g = (const float*)d_in[8];
    const float* ln2b = (const float*)d_in[9];
    const float* W1   = (const float*)d_in[10];
    const float* W2   = (const float*)d_in[11];

    float* out  = (float*)d_out;
    float* kout = out  + (size_t)MTOK * DDIM;
    float* vout = kout + (size_t)MTOK * DDIM;

    float *x2; __half *hh, *cx, *fx, *wt, *qh, *kh, *v16;
    cudaGetSymbolAddress((void**)&x2,  g_x2);
    cudaGetSymbolAddress((void**)&hh,  g_h);
    cudaGetSymbolAddress((void**)&cx,  g_cx);
    cudaGetSymbolAddress((void**)&fx,  g_f);
    cudaGetSymbolAddress((void**)&wt,  g_wt);
    cudaGetSymbolAddress((void**)&qh,  g_qh);
    cudaGetSymbolAddress((void**)&kh,  g_kh);
    cudaGetSymbolAddress((void**)&v16, g_v16);

    const size_t M1 = 1048576;
    __half *wqkv = wt, *wo = wt + 3*M1, *w1 = wt + 4*M1, *w2 = wt + 8*M1;

    cudaFuncSetAttribute(flash_tc, cudaFuncAttributeMaxDynamicSharedMemorySize, FSMEM);
    cudaFuncSetAttribute(mma_gemm<EPI_QKV>,  cudaFuncAttributeMaxDynamicSharedMemorySize, GSMEM);
    cudaFuncSetAttribute(mma_gemm<EPI_GELU>, cudaFuncAttributeMaxDynamicSharedMemorySize, GSMEM);
    cudaFuncSetAttribute(mma_gemm<EPI_RES>,  cudaFuncAttributeMaxDynamicSharedMemorySize, GSMEM);

    dim3 gQKV(3 * DDIM / 128, MTOK / 128);   // (24, 32)
    dim3 gD  (DDIM / 128, MTOK / 128);       // (8, 32)
    dim3 gF  (FF   / 128, MTOK / 128);       // (32, 32)

    wtrans_all<<<3072, 256>>>(Wq, Wk, Wv, Wo, W1, W2, wt);
    ln_k<<<MTOK / 8, 256>>>(x, ln1g, ln1b, hh);
    mma_gemm<EPI_QKV><<<gQKV, 256, GSMEM>>>(hh, wqkv, kout, vout, qh, kh, v16, nullptr, 3*DDIM, DDIM);
    flash_tc<<<dim3(SS / 256, BB * HH), 256, FSMEM>>>(qh, kh, v16, cx);
    mma_gemm<EPI_RES><<<gD, 256, GSMEM>>>(cx, wo, x2, nullptr, nullptr, nullptr, nullptr, x, DDIM, DDIM);
    ln_k<<<MTOK / 8, 256>>>(x2, ln2g, ln2b, hh);
    mma_gemm<EPI_GELU><<<gF, 256, GSMEM>>>(hh, w1, nullptr, nullptr, fx, nullptr, nullptr, nullptr, FF, DDIM);
    mma_gemm<EPI_RES><<<gD, 256, GSMEM>>>(fx, w2, out, nullptr, nullptr, nullptr, nullptr, x2, DDIM, FF);
}